// round 16
// baseline (speedup 1.0000x reference)
#include <cuda_runtime.h>
#include <math.h>
#include <stdint.h>

#define DIM   1024
#define HEADS 16
#define BSZ   2
#define SEQ   2048
#define HD    64
#define ROWS  (BSZ*SEQ)   // 4096

// Scratch (device globals; allocation-free)
__device__ float g_qkv[(size_t)ROWS * 3 * DIM];
__device__ float g_attn[(size_t)ROWS * DIM];
__device__ float g_hid[(size_t)ROWS * 2 * DIM];
__device__ float g_vT[(size_t)BSZ * HEADS * HD * SEQ];   // V transposed [b][h][d][token]
// tf32-rounded copies of inputs (weights stored TRANSPOSED [N][K])
__device__ float g_seq_t[(size_t)ROWS * DIM];
__device__ float g_wqkv_t[(size_t)DIM * 3 * DIM];
__device__ float g_w1_t[(size_t)DIM * 2 * DIM];
__device__ float g_w2_t[(size_t)2 * DIM * DIM];
// mask pre-scaled by log2(e)
__device__ float g_mask_l2e[(size_t)SEQ * SEQ];

// ---------------------------------------------------------------------------
// helpers
// ---------------------------------------------------------------------------
__device__ __forceinline__ void cp16(void* smem_dst, const void* gmem_src) {
    uint32_t d = (uint32_t)__cvta_generic_to_shared(smem_dst);
    asm volatile("cp.async.cg.shared.global [%0], [%1], 16;\n" :: "r"(d), "l"(gmem_src));
}
#define CP_COMMIT() asm volatile("cp.async.commit_group;\n" ::: "memory")
#define CP_WAIT1()  asm volatile("cp.async.wait_group 1;\n" ::: "memory")

__device__ __forceinline__ float f2tf32f(float x) {
    uint32_t r;
    asm("cvt.rna.tf32.f32 %0, %1;" : "=r"(r) : "f"(x));
    return __uint_as_float(r);
}

__device__ __forceinline__ float fexp2(float x) {
    float y;
    asm("ex2.approx.ftz.f32 %0, %1;" : "=f"(y) : "f"(x));
    return y;
}

__device__ __forceinline__ void mma_tf32(float c[4], const uint32_t a[4], const uint32_t* b) {
    asm volatile(
        "mma.sync.aligned.m16n8k8.row.col.f32.tf32.tf32.f32 "
        "{%0,%1,%2,%3}, {%4,%5,%6,%7}, {%8,%9}, {%0,%1,%2,%3};\n"
        : "+f"(c[0]), "+f"(c[1]), "+f"(c[2]), "+f"(c[3])
        : "r"(a[0]), "r"(a[1]), "r"(a[2]), "r"(a[3]), "r"(b[0]), "r"(b[1]));
}

__device__ __forceinline__ void ldsm_x4(uint32_t r[4], uint32_t addr) {
    asm volatile("ldmatrix.sync.aligned.m8n8.x4.shared.b16 {%0,%1,%2,%3}, [%4];"
                 : "=r"(r[0]), "=r"(r[1]), "=r"(r[2]), "=r"(r[3]) : "r"(addr));
}

// ---------------------------------------------------------------------------
// fused tf32 pre-pass (one launch)
// ---------------------------------------------------------------------------
#define CVT_BLOCKS 15360
#define L2E       1.44269504f
#define SCALE_L2E (0.125f * 1.44269504f)

__device__ __forceinline__ void transpose_tile(
    const float* __restrict__ src, float* __restrict__ dst,
    int K, int N, int n0, int k0)
{
    __shared__ float tile[32][33];
    const int tx = threadIdx.x & 31, ty4 = (threadIdx.x >> 5) * 4;
    #pragma unroll
    for (int i = 0; i < 4; i++)
        tile[ty4 + i][tx] = f2tf32f(src[(size_t)(k0 + ty4 + i) * N + n0 + tx]);
    __syncthreads();
    #pragma unroll
    for (int i = 0; i < 4; i++)
        dst[(size_t)(n0 + ty4 + i) * K + k0 + tx] = tile[tx][ty4 + i];
}

__global__ __launch_bounds__(256)
void cvt_all_kernel(const float* __restrict__ seq, float* __restrict__ seq_t,
                    const float* __restrict__ wqkv, float* __restrict__ wqkv_t,
                    const float* __restrict__ w1, float* __restrict__ w1_t,
                    const float* __restrict__ w2, float* __restrict__ w2_t,
                    const float* __restrict__ mask, float* __restrict__ mask_l2e)
{
    int b = blockIdx.x;
    if (b < 4096) {
        size_t i = (size_t)b * 1024 + (size_t)threadIdx.x * 4;
        float4 v = *(const float4*)(seq + i);
        v.x = f2tf32f(v.x); v.y = f2tf32f(v.y);
        v.z = f2tf32f(v.z); v.w = f2tf32f(v.w);
        *(float4*)(seq_t + i) = v;
    } else if (b < 7168) {
        int m = b - 4096;
        transpose_tile(wqkv, wqkv_t, DIM, 3 * DIM, (m % 96) * 32, (m / 96) * 32);
    } else if (b < 9216) {
        int m = b - 7168;
        transpose_tile(w1, w1_t, DIM, 2 * DIM, (m % 64) * 32, (m / 64) * 32);
    } else if (b < 11264) {
        int m = b - 9216;
        transpose_tile(w2, w2_t, 2 * DIM, DIM, (m % 32) * 32, (m / 32) * 32);
    } else {
        size_t i = (size_t)(b - 11264) * 1024 + (size_t)threadIdx.x * 4;
        float4 v = *(const float4*)(mask + i);
        v.x *= L2E; v.y *= L2E; v.z *= L2E; v.w *= L2E;
        *(float4*)(mask_l2e + i) = v;
    }
}

// ---------------------------------------------------------------------------
// tf32 tensor-core GEMM: both operands via ldmatrix.x4.
// q_cols: columns < q_cols scaled by SCALE_L2E (Q folding).
// VT: columns >= 2048 written TRANSPOSED into vt[b][h][d][token] instead of C.
// ---------------------------------------------------------------------------
#define GS 36
#define G_STAGE (128 * GS)
#define GEMM_SMEM_BYTES (6 * G_STAGE * 4)  // 110592

__device__ __forceinline__ void gemm_load_tile(
    const float* __restrict__ A, const float* __restrict__ Bt,
    int K, int bm, int bn, int k0,
    float* Asb, float* Bsb, int tid)
{
    #pragma unroll
    for (int i = 0; i < 4; i++) {
        int id = tid + i * 256;
        int r = id >> 3, q = (id & 7) * 4;
        cp16(Asb + r * GS + q, A  + (size_t)(bm + r) * K + k0 + q);
        cp16(Bsb + r * GS + q, Bt + (size_t)(bn + r) * K + k0 + q);
    }
}

template<int ACT, int ROUND, int VT>
__global__ __launch_bounds__(256, 2)
void tgemm_kernel(const float* __restrict__ A, const float* __restrict__ Bt,
                  const float* __restrict__ bias, float* __restrict__ C,
                  float* __restrict__ vt,
                  int M, int N, int K, int q_cols)
{
    extern __shared__ float smem[];
    float* As = smem;
    float* Bs = smem + 3 * G_STAGE;

    const int tid  = threadIdx.x;
    const int lane = tid & 31;
    const int wid  = tid >> 5;
    const int gid  = lane >> 2;
    const int tig  = lane & 3;
    const int warp_m = wid & 1;
    const int warp_n = wid >> 1;
    const int bm = blockIdx.y * 128;
    const int bn = blockIdx.x * 128;

    const int lf = lane >> 3, lr = lane & 7;
    const uint32_t As_u32 = (uint32_t)__cvta_generic_to_shared(As);
    const uint32_t Bs_u32 = (uint32_t)__cvta_generic_to_shared(Bs);
    const uint32_t aldm = As_u32 +
        (uint32_t)(((warp_m * 64 + (lf & 1) * 8 + lr) * GS + (lf >> 1) * 4) * 4);
    const uint32_t bldm = Bs_u32 +
        (uint32_t)(((warp_n * 32 + (lf >> 1) * 8 + lr) * GS + (lf & 1) * 4) * 4);

    float acc[4][4][4];
    #pragma unroll
    for (int mt = 0; mt < 4; mt++)
        #pragma unroll
        for (int nt = 0; nt < 4; nt++)
            #pragma unroll
            for (int r = 0; r < 4; r++) acc[mt][nt][r] = 0.f;

    const int T = K / 32;
    gemm_load_tile(A, Bt, K, bm, bn, 0,  As,           Bs,           tid); CP_COMMIT();
    gemm_load_tile(A, Bt, K, bm, bn, 32, As + G_STAGE, Bs + G_STAGE, tid); CP_COMMIT();

    for (int t = 0; t < T; t++) {
        CP_WAIT1();
        __syncthreads();

        int tn = t + 2;
        if (tn < T) {
            gemm_load_tile(A, Bt, K, bm, bn, tn * 32,
                           As + (tn % 3) * G_STAGE, Bs + (tn % 3) * G_STAGE, tid);
        }
        CP_COMMIT();

        const uint32_t a_stage = aldm + (uint32_t)((t % 3) * G_STAGE * 4);
        const uint32_t b_stage = bldm + (uint32_t)((t % 3) * G_STAGE * 4);

        #pragma unroll
        for (int kq = 0; kq < 4; kq++) {
            const int k0s = kq * 8;
            uint32_t af[4][4];
            #pragma unroll
            for (int mt = 0; mt < 4; mt++)
                ldsm_x4(af[mt], a_stage + (uint32_t)((mt * 16 * GS + k0s) * 4));

            uint32_t bf0[4], bf1[4];
            ldsm_x4(bf0, b_stage + (uint32_t)(k0s * 4));
            ldsm_x4(bf1, b_stage + (uint32_t)((16 * GS + k0s) * 4));

            #pragma unroll
            for (int mt = 0; mt < 4; mt++) {
                mma_tf32(acc[mt][0], af[mt], bf0);
                mma_tf32(acc[mt][1], af[mt], bf0 + 2);
                mma_tf32(acc[mt][2], af[mt], bf1);
                mma_tf32(acc[mt][3], af[mt], bf1 + 2);
            }
        }
    }

    #pragma unroll
    for (int mt = 0; mt < 4; mt++) {
        const int r0 = bm + warp_m * 64 + mt * 16 + gid;
        #pragma unroll
        for (int nt = 0; nt < 4; nt++) {
            const int c0 = bn + warp_n * 32 + nt * 8 + tig * 2;
            float b0 = 0.f, b1 = 0.f;
            if (bias) { b0 = bias[c0]; b1 = bias[c0 + 1]; }
            float v0 = acc[mt][nt][0] + b0;
            float v1 = acc[mt][nt][1] + b1;
            float v2 = acc[mt][nt][2] + b0;
            float v3 = acc[mt][nt][3] + b1;
            if (ACT == 1) {
                v0 = v0 / (1.f + __expf(-v0));
                v1 = v1 / (1.f + __expf(-v1));
                v2 = v2 / (1.f + __expf(-v2));
                v3 = v3 / (1.f + __expf(-v3));
            }
            if (c0 < q_cols) {
                v0 *= SCALE_L2E; v1 *= SCALE_L2E;
                v2 *= SCALE_L2E; v3 *= SCALE_L2E;
            }
            if (ROUND) {
                v0 = f2tf32f(v0); v1 = f2tf32f(v1);
                v2 = f2tf32f(v2); v3 = f2tf32f(v3);
            }
            if (VT && c0 >= 2 * DIM) {
                // transposed V write: vt[(b*1024 + (c0-2048)) * SEQ + token]
                const int cc = c0 - 2 * DIM;
                const int bbb = r0 >> 11;           // r0 / SEQ
                const int tok = r0 & (SEQ - 1);
                float* p0 = vt + ((size_t)bbb * DIM + cc) * SEQ + tok;
                p0[0]             = v0;
                p0[SEQ]           = v1;   // cc+1
                p0[8]             = v2;   // token+8
                p0[SEQ + 8]       = v3;
            } else {
                *(float2*)(C + (size_t)r0 * N + c0)       = make_float2(v0, v1);
                *(float2*)(C + (size_t)(r0 + 8) * N + c0) = make_float2(v2, v3);
            }
        }
    }
}

// ---------------------------------------------------------------------------
// tf32 tensor-core flash attention.
// Q pre-scaled by 0.125*log2e; mask pre-scaled by log2e loaded into the S
// accumulators. V comes in TRANSPOSED [d][token] -> PV phase uses B-style
// ldmatrix.x4 exactly like the S phase. K and V smem strides 68.
// ---------------------------------------------------------------------------
#define ATS 68
#define KV_STAGE (2 * 64 * ATS)
#define ATTN_SMEM_FLOATS (128 * ATS + 2 * KV_STAGE)
#define ATTN_SMEM_BYTES  (ATTN_SMEM_FLOATS * 4)   // 104448

__device__ __forceinline__ void attn_load_kv(
    const float* kbase, const float* vtbase, int kv0,
    float* Kst, float* Vst, int tid)
{
    #pragma unroll
    for (int i = 0; i < 4; i++) {
        int c = tid + i * 256;
        int r = c >> 4, q = (c & 15) * 4;
        cp16(Kst + r * ATS + q, kbase + (size_t)(kv0 + r) * (3 * DIM) + q);
        // Vt rows are d (0..63), contiguous tokens
        cp16(Vst + r * ATS + q, vtbase + (size_t)r * SEQ + kv0 + q);
    }
}

__global__ __launch_bounds__(256, 2)
void attn_kernel(const float* __restrict__ qkv,
                 const float* __restrict__ vT,
                 const float* __restrict__ mask,   // pre-scaled by log2(e)
                 float* __restrict__ out)
{
    extern __shared__ float smemf[];
    float* Ps = smemf;                // 128 x 68 : Q staging, then P
    float* KV = smemf + 128 * ATS;

    const int tid  = threadIdx.x;
    const int lane = tid & 31;
    const int w    = tid >> 5;
    const int gid  = lane >> 2;
    const int tig  = lane & 3;
    const int bb = blockIdx.z, h = blockIdx.y;
    const int q0 = blockIdx.x * 128;
    const size_t ldq = 3 * DIM;

    const float* qbase  = qkv + (size_t)(bb * SEQ + q0) * ldq + h * HD;
    const float* kbase  = qkv + (size_t)(bb * SEQ) * ldq + DIM + h * HD;
    const float* vtbase = vT + ((size_t)bb * DIM + h * HD) * SEQ;

    const int lf = lane >> 3, lr = lane & 7;
    const uint32_t Ps_u32 = (uint32_t)__cvta_generic_to_shared(Ps);
    const uint32_t KV_u32 = (uint32_t)__cvta_generic_to_shared(KV);
    const uint32_t pldm = Ps_u32 +
        (uint32_t)(((w * 16 + (lf & 1) * 8 + lr) * ATS + (lf >> 1) * 4) * 4);
    const uint32_t kldm_off =
        (uint32_t)((((lf >> 1) * 8 + lr) * ATS + (lf & 1) * 4) * 4);

    #pragma unroll
    for (int i = 0; i < 8; i++) {
        int c = tid + i * 256;
        int r = c >> 4, q = (c & 15) * 4;
        cp16(Ps + r * ATS + q, qbase + (size_t)r * ldq + q);
    }
    attn_load_kv(kbase, vtbase, 0, KV, KV + 64 * ATS, tid);
    CP_COMMIT();

    uint32_t qf[8][4];
    float oacc[8][4];
    #pragma unroll
    for (int nt = 0; nt < 8; nt++)
        #pragma unroll
        for (int r = 0; r < 4; r++) oacc[nt][r] = 0.f;
    float mrow0 = -1e30f, mrow1 = -1e30f, lrow0 = 0.f, lrow1 = 0.f;

    const int qrow = w * 16 + gid;
    const int Rg = q0 + qrow;

    const int NT = SEQ / 64;
    for (int t = 0; t < NT; t++) {
        const int cur = t & 1;
        if (t + 1 < NT) {
            float* Kn = KV + ((t + 1) & 1) * KV_STAGE;
            attn_load_kv(kbase, vtbase, (t + 1) * 64, Kn, Kn + 64 * ATS, tid);
        }
        CP_COMMIT();

        // mask -> S accumulators
        const int kv0 = t * 64;
        const float* mp0 = mask + (size_t)Rg * SEQ + kv0 + 2 * tig;
        const float* mp1 = mp0 + 8 * SEQ;
        float sa[8][4];
        #pragma unroll
        for (int nt = 0; nt < 8; nt++) {
            float2 mk0 = *(const float2*)(mp0 + nt * 8);
            float2 mk1 = *(const float2*)(mp1 + nt * 8);
            sa[nt][0] = mk0.x; sa[nt][1] = mk0.y;
            sa[nt][2] = mk1.x; sa[nt][3] = mk1.y;
        }

        CP_WAIT1();
        __syncthreads();

        if (t == 0) {
            #pragma unroll
            for (int kt = 0; kt < 8; kt++)
                ldsm_x4(qf[kt], pldm + (uint32_t)(kt * 8 * 4));
        }

        const uint32_t kst_u32 = KV_u32 + (uint32_t)(cur * KV_STAGE * 4) + kldm_off;
        const uint32_t vst_u32 = kst_u32 + (uint32_t)(64 * ATS * 4);

        // S = Q'K + mask
        #pragma unroll
        for (int kt = 0; kt < 8; kt++) {
            #pragma unroll
            for (int np = 0; np < 4; np++) {
                uint32_t bfr4[4];
                ldsm_x4(bfr4, kst_u32 + (uint32_t)((np * 16 * ATS + kt * 8) * 4));
                mma_tf32(sa[2 * np],     qf[kt], bfr4);
                mma_tf32(sa[2 * np + 1], qf[kt], bfr4 + 2);
            }
        }

        float mx0 = -1e30f, mx1 = -1e30f;
        #pragma unroll
        for (int nt = 0; nt < 8; nt++) {
            mx0 = fmaxf(mx0, fmaxf(sa[nt][0], sa[nt][1]));
            mx1 = fmaxf(mx1, fmaxf(sa[nt][2], sa[nt][3]));
        }
        mx0 = fmaxf(mx0, __shfl_xor_sync(0xffffffffu, mx0, 1));
        mx0 = fmaxf(mx0, __shfl_xor_sync(0xffffffffu, mx0, 2));
        mx1 = fmaxf(mx1, __shfl_xor_sync(0xffffffffu, mx1, 1));
        mx1 = fmaxf(mx1, __shfl_xor_sync(0xffffffffu, mx1, 2));

        float mn0 = fmaxf(mrow0, mx0);
        float mn1 = fmaxf(mrow1, mx1);
        float alpha0 = fexp2(mrow0 - mn0);
        float alpha1 = fexp2(mrow1 - mn1);
        mrow0 = mn0; mrow1 = mn1;

        float s0a = 0.f, s0b = 0.f, s1a = 0.f, s1b = 0.f;
        #pragma unroll
        for (int nt = 0; nt < 8; nt++) {
            sa[nt][0] = fexp2(sa[nt][0] - mn0);
            sa[nt][1] = fexp2(sa[nt][1] - mn0);
            sa[nt][2] = fexp2(sa[nt][2] - mn1);
            sa[nt][3] = fexp2(sa[nt][3] - mn1);
            if (nt & 1) { s0b += sa[nt][0] + sa[nt][1]; s1b += sa[nt][2] + sa[nt][3]; }
            else        { s0a += sa[nt][0] + sa[nt][1]; s1a += sa[nt][2] + sa[nt][3]; }
        }
        float sum0 = s0a + s0b, sum1 = s1a + s1b;
        sum0 += __shfl_xor_sync(0xffffffffu, sum0, 1);
        sum0 += __shfl_xor_sync(0xffffffffu, sum0, 2);
        sum1 += __shfl_xor_sync(0xffffffffu, sum1, 1);
        sum1 += __shfl_xor_sync(0xffffffffu, sum1, 2);
        lrow0 = lrow0 * alpha0 + sum0;
        lrow1 = lrow1 * alpha1 + sum1;

        #pragma unroll
        for (int nt = 0; nt < 8; nt++) {
            oacc[nt][0] *= alpha0;
            oacc[nt][1] *= alpha0;
            oacc[nt][2] *= alpha1;
            oacc[nt][3] *= alpha1;
        }

        float* pr0 = Ps + qrow * ATS + 2 * tig;
        float* pr1 = pr0 + 8 * ATS;
        #pragma unroll
        for (int nt = 0; nt < 8; nt++) {
            *(float2*)(pr0 + nt * 8) = make_float2(f2tf32f(sa[nt][0]), f2tf32f(sa[nt][1]));
            *(float2*)(pr1 + nt * 8) = make_float2(f2tf32f(sa[nt][2]), f2tf32f(sa[nt][3]));
        }
        __syncwarp();

        // O += P Vt  (both operands via ldmatrix.x4, identical to S phase)
        #pragma unroll
        for (int kt = 0; kt < 8; kt++) {
            uint32_t pf[4];
            ldsm_x4(pf, pldm + (uint32_t)(kt * 8 * 4));
            #pragma unroll
            for (int np = 0; np < 4; np++) {
                uint32_t bfr4[4];
                ldsm_x4(bfr4, vst_u32 + (uint32_t)((np * 16 * ATS + kt * 8) * 4));
                mma_tf32(oacc[2 * np],     pf, bfr4);
                mma_tf32(oacc[2 * np + 1], pf, bfr4 + 2);
            }
        }
        __syncthreads();
    }

    float inv0 = 1.f / lrow0, inv1 = 1.f / lrow1;
    float* o0 = out + (size_t)(bb * SEQ + Rg) * DIM + h * HD + 2 * tig;
    float* o1 = o0 + 8 * DIM;
    #pragma unroll
    for (int nt = 0; nt < 8; nt++) {
        *(float2*)(o0 + nt * 8) = make_float2(f2tf32f(oacc[nt][0] * inv0),
                                              f2tf32f(oacc[nt][1] * inv0));
        *(float2*)(o1 + nt * 8) = make_float2(f2tf32f(oacc[nt][2] * inv1),
                                              f2tf32f(oacc[nt][3] * inv1));
    }
}

// ---------------------------------------------------------------------------
// Launch
// ---------------------------------------------------------------------------
extern "C" void kernel_launch(void* const* d_in, const int* in_sizes, int n_in,
                              void* d_out, int out_size)
{
    const float* seq   = (const float*)d_in[0];
    const float* amask = (const float*)d_in[1];
    const float* Wqkv  = (const float*)d_in[2];
    const float* W1    = (const float*)d_in[3];
    const float* b1    = (const float*)d_in[4];
    const float* W2    = (const float*)d_in[5];
    const float* b2    = (const float*)d_in[6];
    float* out = (float*)d_out;

    float *qkv, *attn, *hid, *vT, *seq_t, *wqkv_t, *w1_t, *w2_t, *mask_l2e;
    cudaGetSymbolAddress((void**)&qkv,      g_qkv);
    cudaGetSymbolAddress((void**)&attn,     g_attn);
    cudaGetSymbolAddress((void**)&hid,      g_hid);
    cudaGetSymbolAddress((void**)&vT,       g_vT);
    cudaGetSymbolAddress((void**)&seq_t,    g_seq_t);
    cudaGetSymbolAddress((void**)&wqkv_t,   g_wqkv_t);
    cudaGetSymbolAddress((void**)&w1_t,     g_w1_t);
    cudaGetSymbolAddress((void**)&w2_t,     g_w2_t);
    cudaGetSymbolAddress((void**)&mask_l2e, g_mask_l2e);

    cudaFuncSetAttribute((const void*)tgemm_kernel<0,1,1>, cudaFuncAttributeMaxDynamicSharedMemorySize, GEMM_SMEM_BYTES);
    cudaFuncSetAttribute((const void*)tgemm_kernel<1,1,0>, cudaFuncAttributeMaxDynamicSharedMemorySize, GEMM_SMEM_BYTES);
    cudaFuncSetAttribute((const void*)tgemm_kernel<0,0,0>, cudaFuncAttributeMaxDynamicSharedMemorySize, GEMM_SMEM_BYTES);
    cudaFuncSetAttribute((const void*)attn_kernel,         cudaFuncAttributeMaxDynamicSharedMemorySize, ATTN_SMEM_BYTES);

    // 0) fused pre-pass: tf32 rounding, weight transposes, mask*log2e
    cvt_all_kernel<<<CVT_BLOCKS, 256>>>(seq, seq_t, Wqkv, wqkv_t, W1, w1_t, W2, w2_t,
                                        amask, mask_l2e);

    // 1) QKV projection (Q scaled by 0.125*log2e; V written transposed to vT)
    {
        dim3 grid(3 * DIM / 128, ROWS / 128);
        tgemm_kernel<0,1,1><<<grid, 256, GEMM_SMEM_BYTES>>>(
            seq_t, wqkv_t, nullptr, qkv, vT, ROWS, 3 * DIM, DIM, DIM);
    }
    // 2) Attention (output rounded: feeds FFN1)
    {
        dim3 grid(SEQ / 128, HEADS, BSZ);
        attn_kernel<<<grid, 256, ATTN_SMEM_BYTES>>>(qkv, vT, mask_l2e, attn);
    }
    // 3) FFN1 + bias + SiLU (output rounded: feeds FFN2)
    {
        dim3 grid(2 * DIM / 128, ROWS / 128);
        tgemm_kernel<1,1,0><<<grid, 256, GEMM_SMEM_BYTES>>>(
            attn, w1_t, b1, hid, nullptr, ROWS, 2 * DIM, DIM, 0);
    }
    // 4) FFN2 + bias (final output: full fp32)
    {
        dim3 grid(DIM / 128, ROWS / 128);
        tgemm_kernel<0,0,0><<<grid, 256, GEMM_SMEM_BYTES>>>(
            hid, w2_t, b2, out, nullptr, ROWS, DIM, 2 * DIM, 0);
    }
}

// round 17
// speedup vs baseline: 1.7308x; 1.7308x over previous
#include <cuda_runtime.h>
#include <cuda_fp16.h>
#include <math.h>
#include <stdint.h>

#define DIM   1024
#define HEADS 16
#define BSZ   2
#define SEQ   2048
#define HD    64
#define ROWS  (BSZ*SEQ)   // 4096

// Scratch (device globals; allocation-free). Activations/weights in fp16.
__device__ __half g_qkv[(size_t)ROWS * 3 * DIM];
__device__ __half g_attn[(size_t)ROWS * DIM];
__device__ __half g_hid[(size_t)ROWS * 2 * DIM];
__device__ __half g_seq_h[(size_t)ROWS * DIM];
__device__ __half g_wqkv_h[(size_t)DIM * 3 * DIM];   // transposed [N][K]
__device__ __half g_w1_h[(size_t)DIM * 2 * DIM];     // transposed
__device__ __half g_w2_h[(size_t)2 * DIM * DIM];     // transposed
__device__ float  g_mask_l2e[(size_t)SEQ * SEQ];

// ---------------------------------------------------------------------------
// helpers
// ---------------------------------------------------------------------------
__device__ __forceinline__ void cp16(void* smem_dst, const void* gmem_src) {
    uint32_t d = (uint32_t)__cvta_generic_to_shared(smem_dst);
    asm volatile("cp.async.cg.shared.global [%0], [%1], 16;\n" :: "r"(d), "l"(gmem_src));
}
#define CP_COMMIT() asm volatile("cp.async.commit_group;\n" ::: "memory")
#define CP_WAIT1()  asm volatile("cp.async.wait_group 1;\n" ::: "memory")

__device__ __forceinline__ float fexp2(float x) {
    float y;
    asm("ex2.approx.ftz.f32 %0, %1;" : "=f"(y) : "f"(x));
    return y;
}

__device__ __forceinline__ void mma_f16(float c[4], const uint32_t a[4], const uint32_t* b) {
    asm volatile(
        "mma.sync.aligned.m16n8k16.row.col.f32.f16.f16.f32 "
        "{%0,%1,%2,%3}, {%4,%5,%6,%7}, {%8,%9}, {%0,%1,%2,%3};\n"
        : "+f"(c[0]), "+f"(c[1]), "+f"(c[2]), "+f"(c[3])
        : "r"(a[0]), "r"(a[1]), "r"(a[2]), "r"(a[3]), "r"(b[0]), "r"(b[1]));
}

__device__ __forceinline__ void ldsm_x4(uint32_t r[4], uint32_t addr) {
    asm volatile("ldmatrix.sync.aligned.m8n8.x4.shared.b16 {%0,%1,%2,%3}, [%4];"
                 : "=r"(r[0]), "=r"(r[1]), "=r"(r[2]), "=r"(r[3]) : "r"(addr));
}
__device__ __forceinline__ void ldsm_x4t(uint32_t r[4], uint32_t addr) {
    asm volatile("ldmatrix.sync.aligned.m8n8.x4.trans.shared.b16 {%0,%1,%2,%3}, [%4];"
                 : "=r"(r[0]), "=r"(r[1]), "=r"(r[2]), "=r"(r[3]) : "r"(addr));
}

// ---------------------------------------------------------------------------
// fused pre-pass (one launch):
//  [0,4096)        seq fp32 -> fp16
//  [4096,7168)     Wqkv transpose + fp16  (96 x 32 tiles)
//  [7168,9216)     W1 transpose + fp16    (64 x 32 tiles)
//  [9216,11264)    W2 transpose + fp16    (32 x 64 tiles)
//  [11264,15360)   mask * log2(e) (fp32)
// ---------------------------------------------------------------------------
#define CVT_BLOCKS 15360
#define L2E       1.44269504f
#define SCALE_L2E (0.125f * 1.44269504f)

__device__ __forceinline__ void transpose_tile_h(
    const float* __restrict__ src, __half* __restrict__ dst,
    int K, int N, int n0, int k0)
{
    __shared__ float tile[32][33];
    const int tx = threadIdx.x & 31, ty4 = (threadIdx.x >> 5) * 4;
    #pragma unroll
    for (int i = 0; i < 4; i++)
        tile[ty4 + i][tx] = src[(size_t)(k0 + ty4 + i) * N + n0 + tx];
    __syncthreads();
    #pragma unroll
    for (int i = 0; i < 4; i++)
        dst[(size_t)(n0 + ty4 + i) * K + k0 + tx] = __float2half_rn(tile[tx][ty4 + i]);
}

__global__ __launch_bounds__(256)
void cvt_all_kernel(const float* __restrict__ seq, __half* __restrict__ seq_h,
                    const float* __restrict__ wqkv, __half* __restrict__ wqkv_h,
                    const float* __restrict__ w1, __half* __restrict__ w1_h,
                    const float* __restrict__ w2, __half* __restrict__ w2_h,
                    const float* __restrict__ mask, float* __restrict__ mask_l2e)
{
    int b = blockIdx.x;
    if (b < 4096) {
        size_t i = (size_t)b * 1024 + (size_t)threadIdx.x * 4;
        float4 v = *(const float4*)(seq + i);
        *(__half2*)(seq_h + i)     = __floats2half2_rn(v.x, v.y);
        *(__half2*)(seq_h + i + 2) = __floats2half2_rn(v.z, v.w);
    } else if (b < 7168) {
        int m = b - 4096;
        transpose_tile_h(wqkv, wqkv_h, DIM, 3 * DIM, (m % 96) * 32, (m / 96) * 32);
    } else if (b < 9216) {
        int m = b - 7168;
        transpose_tile_h(w1, w1_h, DIM, 2 * DIM, (m % 64) * 32, (m / 64) * 32);
    } else if (b < 11264) {
        int m = b - 9216;
        transpose_tile_h(w2, w2_h, 2 * DIM, DIM, (m % 32) * 32, (m / 32) * 32);
    } else {
        size_t i = (size_t)(b - 11264) * 1024 + (size_t)threadIdx.x * 4;
        float4 v = *(const float4*)(mask + i);
        v.x *= L2E; v.y *= L2E; v.z *= L2E; v.w *= L2E;
        *(float4*)(mask_l2e + i) = v;
    }
}

// ---------------------------------------------------------------------------
// fp16 tensor-core GEMM: C = A[M,K] @ Bt[N,K]^T (+bias)(+SiLU).
// 128x128 tile, BK=64, 3-stage cp.async ring, m16n8k16 MMA,
// both operands via ldmatrix.x4. Smem row stride 72 halfs (144B).
// ---------------------------------------------------------------------------
#define GSH 72
#define G_STAGE_H (128 * GSH)                       // halfs
#define GEMM_SMEM_BYTES (6 * G_STAGE_H * 2)         // 110592

__device__ __forceinline__ void gemm_load_tile(
    const __half* __restrict__ A, const __half* __restrict__ Bt,
    int K, int bm, int bn, int k0,
    __half* Asb, __half* Bsb, int tid)
{
    #pragma unroll
    for (int i = 0; i < 4; i++) {
        int id = tid + i * 256;               // 0..1023
        int r = id >> 3, ch = id & 7;         // 128 rows x 8 16B-chunks (8 halfs)
        cp16(Asb + r * GSH + ch * 8, A  + (size_t)(bm + r) * K + k0 + ch * 8);
        cp16(Bsb + r * GSH + ch * 8, Bt + (size_t)(bn + r) * K + k0 + ch * 8);
    }
}

template<int ACT, int HOUT>
__global__ __launch_bounds__(256, 2)
void tgemm_kernel(const __half* __restrict__ A, const __half* __restrict__ Bt,
                  const float* __restrict__ bias, void* __restrict__ Cv,
                  int M, int N, int K, int q_cols)
{
    extern __shared__ __half smh[];
    __half* As = smh;
    __half* Bs = smh + 3 * G_STAGE_H;

    const int tid  = threadIdx.x;
    const int lane = tid & 31;
    const int wid  = tid >> 5;
    const int gid  = lane >> 2;
    const int tig  = lane & 3;
    const int warp_m = wid & 1;
    const int warp_n = wid >> 1;
    const int bm = blockIdx.y * 128;
    const int bn = blockIdx.x * 128;

    const int lf = lane >> 3, lr = lane & 7;
    const uint32_t As_u32 = (uint32_t)__cvta_generic_to_shared(As);
    const uint32_t Bs_u32 = (uint32_t)__cvta_generic_to_shared(Bs);
    // A-frag x4: row = (f&1)*8+r (m), byte col = (f>>1)*16 (k half)
    const uint32_t aldm = As_u32 +
        (uint32_t)(((warp_m * 64 + (lf & 1) * 8 + lr) * GSH + (lf >> 1) * 8) * 2);
    // B-frag x4 (two n-tiles): row = (f>>1)*8+r (n), byte col = (f&1)*16 (k half)
    const uint32_t bldm = Bs_u32 +
        (uint32_t)(((warp_n * 32 + (lf >> 1) * 8 + lr) * GSH + (lf & 1) * 8) * 2);

    float acc[4][4][4];
    #pragma unroll
    for (int mt = 0; mt < 4; mt++)
        #pragma unroll
        for (int nt = 0; nt < 4; nt++)
            #pragma unroll
            for (int r = 0; r < 4; r++) acc[mt][nt][r] = 0.f;

    const int T = K / 64;
    gemm_load_tile(A, Bt, K, bm, bn, 0,  As,             Bs,             tid); CP_COMMIT();
    gemm_load_tile(A, Bt, K, bm, bn, 64, As + G_STAGE_H, Bs + G_STAGE_H, tid); CP_COMMIT();

    for (int t = 0; t < T; t++) {
        CP_WAIT1();
        __syncthreads();

        int tn = t + 2;
        if (tn < T) {
            gemm_load_tile(A, Bt, K, bm, bn, tn * 64,
                           As + (tn % 3) * G_STAGE_H, Bs + (tn % 3) * G_STAGE_H, tid);
        }
        CP_COMMIT();

        const uint32_t a_stage = aldm + (uint32_t)((t % 3) * G_STAGE_H * 2);
        const uint32_t b_stage = bldm + (uint32_t)((t % 3) * G_STAGE_H * 2);

        #pragma unroll
        for (int kt = 0; kt < 4; kt++) {        // k16 steps within BK=64
            const uint32_t koff = (uint32_t)(kt * 32);  // 16 halfs
            uint32_t af[4][4];
            #pragma unroll
            for (int mt = 0; mt < 4; mt++)
                ldsm_x4(af[mt], a_stage + (uint32_t)(mt * 16 * GSH * 2) + koff);

            uint32_t bf[2][4];
            #pragma unroll
            for (int np = 0; np < 2; np++)
                ldsm_x4(bf[np], b_stage + (uint32_t)(np * 16 * GSH * 2) + koff);

            #pragma unroll
            for (int mt = 0; mt < 4; mt++) {
                mma_f16(acc[mt][0], af[mt], bf[0]);
                mma_f16(acc[mt][1], af[mt], bf[0] + 2);
                mma_f16(acc[mt][2], af[mt], bf[1]);
                mma_f16(acc[mt][3], af[mt], bf[1] + 2);
            }
        }
    }

    #pragma unroll
    for (int mt = 0; mt < 4; mt++) {
        const int r0 = bm + warp_m * 64 + mt * 16 + gid;
        #pragma unroll
        for (int nt = 0; nt < 4; nt++) {
            const int c0 = bn + warp_n * 32 + nt * 8 + tig * 2;
            float b0 = 0.f, b1 = 0.f;
            if (bias) { b0 = bias[c0]; b1 = bias[c0 + 1]; }
            float v0 = acc[mt][nt][0] + b0;
            float v1 = acc[mt][nt][1] + b1;
            float v2 = acc[mt][nt][2] + b0;
            float v3 = acc[mt][nt][3] + b1;
            if (ACT == 1) {
                v0 = v0 / (1.f + __expf(-v0));
                v1 = v1 / (1.f + __expf(-v1));
                v2 = v2 / (1.f + __expf(-v2));
                v3 = v3 / (1.f + __expf(-v3));
            }
            if (c0 < q_cols) {
                v0 *= SCALE_L2E; v1 *= SCALE_L2E;
                v2 *= SCALE_L2E; v3 *= SCALE_L2E;
            }
            if (HOUT) {
                __half* C = (__half*)Cv;
                *(__half2*)(C + (size_t)r0 * N + c0)       = __floats2half2_rn(v0, v1);
                *(__half2*)(C + (size_t)(r0 + 8) * N + c0) = __floats2half2_rn(v2, v3);
            } else {
                float* C = (float*)Cv;
                *(float2*)(C + (size_t)r0 * N + c0)       = make_float2(v0, v1);
                *(float2*)(C + (size_t)(r0 + 8) * N + c0) = make_float2(v2, v3);
            }
        }
    }
}

// ---------------------------------------------------------------------------
// fp16 tensor-core flash attention.
// Q pre-scaled by 0.125*log2e (QKV epilogue); mask (fp32, *log2e) loaded into
// the S accumulators. S: K via ldmatrix.x4 (two n-tiles). PV: V via
// ldmatrix.x4.trans (native b16 transpose). All smem strides 72 halfs.
// ---------------------------------------------------------------------------
#define ATSH 72
#define KV_STAGE_H (2 * 64 * ATSH)                 // K + V, halfs
#define ATTN_SMEM_BYTES ((128 * ATSH + 2 * KV_STAGE_H) * 2)  // 55296

__device__ __forceinline__ void attn_load_kv(
    const __half* kbase, const __half* vbase, int kv0,
    __half* Kst, __half* Vst, int tid)
{
    #pragma unroll
    for (int i = 0; i < 2; i++) {
        int c = tid + i * 256;            // 0..511
        int r = c >> 3, ch = c & 7;       // 64 rows x 8 chunks
        cp16(Kst + r * ATSH + ch * 8, kbase + (size_t)(kv0 + r) * (3 * DIM) + ch * 8);
        cp16(Vst + r * ATSH + ch * 8, vbase + (size_t)(kv0 + r) * (3 * DIM) + ch * 8);
    }
}

__global__ __launch_bounds__(256, 2)
void attn_kernel(const __half* __restrict__ qkv,
                 const float* __restrict__ mask,   // pre-scaled by log2(e)
                 __half* __restrict__ out)
{
    extern __shared__ __half smh[];
    __half* Ps = smh;                 // 128 x 72 halfs : Q staging, then P
    __half* KV = smh + 128 * ATSH;

    const int tid  = threadIdx.x;
    const int lane = tid & 31;
    const int w    = tid >> 5;
    const int gid  = lane >> 2;
    const int tig  = lane & 3;
    const int bb = blockIdx.z, h = blockIdx.y;
    const int q0 = blockIdx.x * 128;
    const size_t ldq = 3 * DIM;

    const __half* qbase = qkv + (size_t)(bb * SEQ + q0) * ldq + h * HD;
    const __half* kbase = qkv + (size_t)(bb * SEQ) * ldq + DIM + h * HD;
    const __half* vbase = kbase + DIM;

    const int lf = lane >> 3, lr = lane & 7;
    const uint32_t Ps_u32 = (uint32_t)__cvta_generic_to_shared(Ps);
    const uint32_t KV_u32 = (uint32_t)__cvta_generic_to_shared(KV);
    // A-style (Q/P): row = w*16 + (f&1)*8 + r, byte = (f>>1)*16
    const uint32_t pldm = Ps_u32 +
        (uint32_t)(((w * 16 + (lf & 1) * 8 + lr) * ATSH + (lf >> 1) * 8) * 2);
    // B-style (K): row = (f>>1)*8 + r, byte = (f&1)*16
    const uint32_t kldm_off =
        (uint32_t)((((lf >> 1) * 8 + lr) * ATSH + (lf & 1) * 8) * 2);
    // trans-B (V): row(kv) = (f&1)*8 + r, byte(d) = (f>>1)*16
    const uint32_t vldm_off =
        (uint32_t)((((lf & 1) * 8 + lr) * ATSH + (lf >> 1) * 8) * 2);

    // stage Q (128 x 64 halfs)
    #pragma unroll
    for (int i = 0; i < 4; i++) {
        int c = tid + i * 256;
        int r = c >> 3, ch = c & 7;
        cp16(Ps + r * ATSH + ch * 8, qbase + (size_t)r * ldq + ch * 8);
    }
    attn_load_kv(kbase, vbase, 0, KV, KV + 64 * ATSH, tid);
    CP_COMMIT();

    uint32_t qf[4][4];
    float oacc[8][4];
    #pragma unroll
    for (int nt = 0; nt < 8; nt++)
        #pragma unroll
        for (int r = 0; r < 4; r++) oacc[nt][r] = 0.f;
    float mrow0 = -1e30f, mrow1 = -1e30f, lrow0 = 0.f, lrow1 = 0.f;

    const int qrow = w * 16 + gid;
    const int Rg = q0 + qrow;

    const int NT = SEQ / 64;
    for (int t = 0; t < NT; t++) {
        const int cur = t & 1;
        if (t + 1 < NT) {
            __half* Kn = KV + ((t + 1) & 1) * KV_STAGE_H;
            attn_load_kv(kbase, vbase, (t + 1) * 64, Kn, Kn + 64 * ATSH, tid);
        }
        CP_COMMIT();

        // mask -> S accumulators
        const int kv0 = t * 64;
        const float* mp0 = mask + (size_t)Rg * SEQ + kv0 + 2 * tig;
        const float* mp1 = mp0 + 8 * SEQ;
        float sa[8][4];
        #pragma unroll
        for (int nt = 0; nt < 8; nt++) {
            float2 mk0 = *(const float2*)(mp0 + nt * 8);
            float2 mk1 = *(const float2*)(mp1 + nt * 8);
            sa[nt][0] = mk0.x; sa[nt][1] = mk0.y;
            sa[nt][2] = mk1.x; sa[nt][3] = mk1.y;
        }

        CP_WAIT1();
        __syncthreads();

        if (t == 0) {
            #pragma unroll
            for (int kt = 0; kt < 4; kt++)
                ldsm_x4(qf[kt], pldm + (uint32_t)(kt * 32));
        }

        const uint32_t kst = KV_u32 + (uint32_t)(cur * KV_STAGE_H * 2) + kldm_off;
        const uint32_t vst = KV_u32 + (uint32_t)((cur * KV_STAGE_H + 64 * ATSH) * 2) + vldm_off;

        // S = Q'K + mask
        #pragma unroll
        for (int kt = 0; kt < 4; kt++) {
            #pragma unroll
            for (int np = 0; np < 4; np++) {
                uint32_t bfr4[4];
                ldsm_x4(bfr4, kst + (uint32_t)(np * 16 * ATSH * 2 + kt * 32));
                mma_f16(sa[2 * np],     qf[kt], bfr4);
                mma_f16(sa[2 * np + 1], qf[kt], bfr4 + 2);
            }
        }

        float mx0 = -1e30f, mx1 = -1e30f;
        #pragma unroll
        for (int nt = 0; nt < 8; nt++) {
            mx0 = fmaxf(mx0, fmaxf(sa[nt][0], sa[nt][1]));
            mx1 = fmaxf(mx1, fmaxf(sa[nt][2], sa[nt][3]));
        }
        mx0 = fmaxf(mx0, __shfl_xor_sync(0xffffffffu, mx0, 1));
        mx0 = fmaxf(mx0, __shfl_xor_sync(0xffffffffu, mx0, 2));
        mx1 = fmaxf(mx1, __shfl_xor_sync(0xffffffffu, mx1, 1));
        mx1 = fmaxf(mx1, __shfl_xor_sync(0xffffffffu, mx1, 2));

        float mn0 = fmaxf(mrow0, mx0);
        float mn1 = fmaxf(mrow1, mx1);
        float alpha0 = fexp2(mrow0 - mn0);
        float alpha1 = fexp2(mrow1 - mn1);
        mrow0 = mn0; mrow1 = mn1;

        float s0a = 0.f, s0b = 0.f, s1a = 0.f, s1b = 0.f;
        #pragma unroll
        for (int nt = 0; nt < 8; nt++) {
            sa[nt][0] = fexp2(sa[nt][0] - mn0);
            sa[nt][1] = fexp2(sa[nt][1] - mn0);
            sa[nt][2] = fexp2(sa[nt][2] - mn1);
            sa[nt][3] = fexp2(sa[nt][3] - mn1);
            if (nt & 1) { s0b += sa[nt][0] + sa[nt][1]; s1b += sa[nt][2] + sa[nt][3]; }
            else        { s0a += sa[nt][0] + sa[nt][1]; s1a += sa[nt][2] + sa[nt][3]; }
        }
        float sum0 = s0a + s0b, sum1 = s1a + s1b;
        sum0 += __shfl_xor_sync(0xffffffffu, sum0, 1);
        sum0 += __shfl_xor_sync(0xffffffffu, sum0, 2);
        sum1 += __shfl_xor_sync(0xffffffffu, sum1, 1);
        sum1 += __shfl_xor_sync(0xffffffffu, sum1, 2);
        lrow0 = lrow0 * alpha0 + sum0;
        lrow1 = lrow1 * alpha1 + sum1;

        #pragma unroll
        for (int nt = 0; nt < 8; nt++) {
            oacc[nt][0] *= alpha0;
            oacc[nt][1] *= alpha0;
            oacc[nt][2] *= alpha1;
            oacc[nt][3] *= alpha1;
        }

        // store P as fp16 (per-warp private rows)
        __half* pr0 = Ps + qrow * ATSH + 2 * tig;
        __half* pr1 = pr0 + 8 * ATSH;
        #pragma unroll
        for (int nt = 0; nt < 8; nt++) {
            *(__half2*)(pr0 + nt * 8) = __floats2half2_rn(sa[nt][0], sa[nt][1]);
            *(__half2*)(pr1 + nt * 8) = __floats2half2_rn(sa[nt][2], sa[nt][3]);
        }
        __syncwarp();

        // O += P V : P via ldmatrix.x4, V via ldmatrix.x4.trans
        #pragma unroll
        for (int kt = 0; kt < 4; kt++) {          // kv 16-steps
            uint32_t pf[4];
            ldsm_x4(pf, pldm + (uint32_t)(kt * 32));
            #pragma unroll
            for (int np = 0; np < 4; np++) {      // d 16-chunks
                uint32_t v4[4];
                ldsm_x4t(v4, vst + (uint32_t)(kt * 16 * ATSH * 2 + np * 32));
                mma_f16(oacc[2 * np],     pf, v4);
                mma_f16(oacc[2 * np + 1], pf, v4 + 2);
            }
        }
        __syncthreads();
    }

    float inv0 = 1.f / lrow0, inv1 = 1.f / lrow1;
    __half* o0 = out + (size_t)(bb * SEQ + Rg) * DIM + h * HD + 2 * tig;
    __half* o1 = o0 + 8 * DIM;
    #pragma unroll
    for (int nt = 0; nt < 8; nt++) {
        *(__half2*)(o0 + nt * 8) = __floats2half2_rn(oacc[nt][0] * inv0, oacc[nt][1] * inv0);
        *(__half2*)(o1 + nt * 8) = __floats2half2_rn(oacc[nt][2] * inv1, oacc[nt][3] * inv1);
    }
}

// ---------------------------------------------------------------------------
// Launch
// ---------------------------------------------------------------------------
extern "C" void kernel_launch(void* const* d_in, const int* in_sizes, int n_in,
                              void* d_out, int out_size)
{
    const float* seq   = (const float*)d_in[0];
    const float* amask = (const float*)d_in[1];
    const float* Wqkv  = (const float*)d_in[2];
    const float* W1    = (const float*)d_in[3];
    const float* b1    = (const float*)d_in[4];
    const float* W2    = (const float*)d_in[5];
    const float* b2    = (const float*)d_in[6];
    float* out = (float*)d_out;

    __half *qkv, *attn, *hid, *seq_h, *wqkv_h, *w1_h, *w2_h;
    float *mask_l2e;
    cudaGetSymbolAddress((void**)&qkv,      g_qkv);
    cudaGetSymbolAddress((void**)&attn,     g_attn);
    cudaGetSymbolAddress((void**)&hid,      g_hid);
    cudaGetSymbolAddress((void**)&seq_h,    g_seq_h);
    cudaGetSymbolAddress((void**)&wqkv_h,   g_wqkv_h);
    cudaGetSymbolAddress((void**)&w1_h,     g_w1_h);
    cudaGetSymbolAddress((void**)&w2_h,     g_w2_h);
    cudaGetSymbolAddress((void**)&mask_l2e, g_mask_l2e);

    cudaFuncSetAttribute((const void*)tgemm_kernel<0,1>, cudaFuncAttributeMaxDynamicSharedMemorySize, GEMM_SMEM_BYTES);
    cudaFuncSetAttribute((const void*)tgemm_kernel<1,1>, cudaFuncAttributeMaxDynamicSharedMemorySize, GEMM_SMEM_BYTES);
    cudaFuncSetAttribute((const void*)tgemm_kernel<0,0>, cudaFuncAttributeMaxDynamicSharedMemorySize, GEMM_SMEM_BYTES);
    cudaFuncSetAttribute((const void*)attn_kernel,       cudaFuncAttributeMaxDynamicSharedMemorySize, ATTN_SMEM_BYTES);

    // 0) fused pre-pass: fp16 conversion, weight transposes, mask*log2e
    cvt_all_kernel<<<CVT_BLOCKS, 256>>>(seq, seq_h, Wqkv, wqkv_h, W1, w1_h, W2, w2_h,
                                        amask, mask_l2e);

    // 1) QKV projection (Q scaled by 0.125*log2e; fp16 out)
    {
        dim3 grid(3 * DIM / 128, ROWS / 128);
        tgemm_kernel<0,1><<<grid, 256, GEMM_SMEM_BYTES>>>(
            seq_h, wqkv_h, nullptr, qkv, ROWS, 3 * DIM, DIM, DIM);
    }
    // 2) Attention (fp16 out)
    {
        dim3 grid(SEQ / 128, HEADS, BSZ);
        attn_kernel<<<grid, 256, ATTN_SMEM_BYTES>>>(qkv, mask_l2e, attn);
    }
    // 3) FFN1 + bias + SiLU (fp16 out)
    {
        dim3 grid(2 * DIM / 128, ROWS / 128);
        tgemm_kernel<1,1><<<grid, 256, GEMM_SMEM_BYTES>>>(
            attn, w1_h, b1, hid, ROWS, 2 * DIM, DIM, 0);
    }
    // 4) FFN2 + bias (fp32 out)
    {
        dim3 grid(DIM / 128, ROWS / 128);
        tgemm_kernel<0,0><<<grid, 256, GEMM_SMEM_BYTES>>>(
            hid, w2_h, b2, out, ROWS, DIM, 2 * DIM, 0);
    }
}